// round 1
// baseline (speedup 1.0000x reference)
#include <cuda_runtime.h>
#include <cstdint>

// Problem dims (fixed)
#define Bq 2
#define Vq 8
#define Tq 4
#define Nq 1024
#define Dq 16
#define F_INq 64
#define F_OUTq 64
#define Rq 16
#define RVq 4
#define BV (Bq*Vq)                 // 16
#define ROWS_PER_BV (Tq*Nq*Dq)     // 65536
#define RPB 128                    // rows per block
#define TPB 128                    // threads per block (1 row / thread)
#define XS_STRIDE 66               // padded smem row stride (floats), even for 8B-aligned f32x2

// Scratch: per-(b,v) H = (sum_A fv[A]*core[A]) @ fac_out  -> (16 x 64), plus fac_in^T (64 x 16)
__device__ float g_H[BV * Rq * F_OUTq];     // 16*16*64
__device__ float g_finT[F_INq * Rq];        // 64*16

// ---- packed f32x2 helpers -------------------------------------------------
__device__ __forceinline__ unsigned long long ffma2(unsigned long long a,
                                                    unsigned long long b,
                                                    unsigned long long c) {
    unsigned long long d;
    asm("fma.rn.f32x2 %0, %1, %2, %3;" : "=l"(d) : "l"(a), "l"(b), "l"(c));
    return d;
}
__device__ __forceinline__ unsigned long long pack2(float lo, float hi) {
    unsigned long long d;
    asm("mov.b64 %0, {%1, %2};" : "=l"(d) : "f"(lo), "f"(hi));
    return d;
}
__device__ __forceinline__ void unpack2(unsigned long long v, float& lo, float& hi) {
    asm("mov.b64 {%0, %1}, %2;" : "=f"(lo), "=f"(hi) : "l"(v));
}

// ---- tiny precompute: Ceff and H per (b,v), plus fac_in^T -----------------
__global__ void precompute_kernel(const int* __restrict__ var_idx,
                                  const float* __restrict__ core,        // (RV, R, R)
                                  const float* __restrict__ factor_vars, // (NVAR, RV)
                                  const float* __restrict__ fac_in,      // (R, F_IN)
                                  const float* __restrict__ fac_out) {   // (R, F_OUT)
    int bv = blockIdx.x;       // 0..15
    int e  = threadIdx.x;      // 0..63
    __shared__ float fvs[RVq];
    __shared__ float ceff[Rq * Rq];

    if (e < RVq) fvs[e] = factor_vars[var_idx[bv] * RVq + e];
    __syncthreads();

    for (int i = e; i < Rq * Rq; i += 64) {
        float s = 0.f;
        #pragma unroll
        for (int A = 0; A < RVq; ++A) s += fvs[A] * core[A * Rq * Rq + i];
        ceff[i] = s;
    }
    __syncthreads();

    #pragma unroll
    for (int r = 0; r < Rq; ++r) {
        float s = 0.f;
        #pragma unroll
        for (int c = 0; c < Rq; ++c) s += ceff[r * Rq + c] * fac_out[c * F_OUTq + e];
        g_H[bv * Rq * F_OUTq + r * F_OUTq + e] = s;
    }
    if (bv == 0) {
        #pragma unroll
        for (int r = 0; r < Rq; ++r) g_finT[e * Rq + r] = fac_in[r * F_INq + e];
    }
}

// ---- main fused kernel -----------------------------------------------------
// out[row, e] = sum_r ( sum_a x[row, a] * finT[a][r] ) * H[bv][r][e]
__global__ void __launch_bounds__(TPB, 4)
tucker_main_kernel(const float* __restrict__ x, float* __restrict__ out) {
    __shared__ float xs[RPB * XS_STRIDE];          // 33792 B, reused for output
    __shared__ float sH[Rq * F_OUTq];              // 4 KB
    __shared__ float sfinT[F_INq * Rq];            // 4 KB

    const int bv = blockIdx.y;
    const int t  = threadIdx.x;
    const size_t base = ((size_t)bv * ROWS_PER_BV + (size_t)blockIdx.x * RPB) * (size_t)F_INq;

    // stage shared tables
    for (int i = t; i < Rq * F_OUTq; i += TPB)  sH[i]    = g_H[bv * Rq * F_OUTq + i];
    for (int i = t; i < F_INq * Rq;  i += TPB)  sfinT[i] = g_finT[i];

    // stage x tile (contiguous 32 KB) via float2, into padded rows
    const float2* gx = (const float2*)(x + base);
    #pragma unroll 4
    for (int it = 0; it < (RPB * F_INq / 2) / TPB; ++it) {   // 32 iters
        int i = it * TPB + t;
        float2 v = gx[i];
        int row = i >> 5;          // 32 float2 per row
        int c2  = i & 31;
        *(float2*)&xs[row * XS_STRIDE + c2 * 2] = v;
    }
    __syncthreads();

    float* xrow = &xs[t * XS_STRIDE];

    // ---- stage 1: y[r] = sum_a x[a] * finT[a][r]  (packed over r-pairs)
    unsigned long long y2[Rq / 2];
    #pragma unroll
    for (int j = 0; j < Rq / 2; ++j) y2[j] = 0ull;

    #pragma unroll 4
    for (int a = 0; a < F_INq; ++a) {
        float xa = xrow[a];
        unsigned long long xa2 = pack2(xa, xa);
        const ulonglong2* f = (const ulonglong2*)&sfinT[a * Rq];  // uniform broadcast
        #pragma unroll
        for (int j = 0; j < 4; ++j) {
            ulonglong2 u = f[j];
            y2[2 * j]     = ffma2(xa2, u.x, y2[2 * j]);
            y2[2 * j + 1] = ffma2(xa2, u.y, y2[2 * j + 1]);
        }
    }
    float y[Rq];
    #pragma unroll
    for (int j = 0; j < Rq / 2; ++j) unpack2(y2[j], y[2 * j], y[2 * j + 1]);

    // ---- stage 2: out[e] = sum_r y[r] * H[r][e]  (packed over e-pairs)
    unsigned long long o2[F_OUTq / 2];
    #pragma unroll
    for (int j = 0; j < F_OUTq / 2; ++j) o2[j] = 0ull;

    #pragma unroll 2
    for (int r = 0; r < Rq; ++r) {
        unsigned long long yr2 = pack2(y[r], y[r]);
        const ulonglong2* h = (const ulonglong2*)&sH[r * F_OUTq];  // uniform broadcast
        #pragma unroll
        for (int q = 0; q < F_OUTq / 4; ++q) {   // 16 x LDS.128 -> 32 packed operands
            ulonglong2 u = h[q];
            o2[2 * q]     = ffma2(yr2, u.x, o2[2 * q]);
            o2[2 * q + 1] = ffma2(yr2, u.y, o2[2 * q + 1]);
        }
    }

    // write result back into own smem row (8B aligned: stride 66 floats)
    #pragma unroll
    for (int j = 0; j < F_OUTq / 2; ++j)
        *(unsigned long long*)&xrow[2 * j] = o2[j];
    __syncthreads();

    // coalesced store
    float2* gout = (float2*)(out + base);
    #pragma unroll 4
    for (int it = 0; it < (RPB * F_OUTq / 2) / TPB; ++it) {
        int i = it * TPB + t;
        int row = i >> 5;
        int c2  = i & 31;
        gout[i] = *(const float2*)&xs[row * XS_STRIDE + c2 * 2];
    }
}

extern "C" void kernel_launch(void* const* d_in, const int* in_sizes, int n_in,
                              void* d_out, int out_size) {
    const float* x           = (const float*)d_in[0];
    const int*   var_idx     = (const int*)d_in[1];
    const float* core        = (const float*)d_in[2];
    const float* factor_vars = (const float*)d_in[3];
    const float* fac_in      = (const float*)d_in[4];
    const float* fac_out     = (const float*)d_in[5];
    float* out = (float*)d_out;

    precompute_kernel<<<BV, 64>>>(var_idx, core, factor_vars, fac_in, fac_out);

    dim3 grid(ROWS_PER_BV / RPB, BV);   // (512, 16)
    tucker_main_kernel<<<grid, TPB>>>(x, out);
}

// round 2
// speedup vs baseline: 1.5569x; 1.5569x over previous
#include <cuda_runtime.h>
#include <cstdint>

// Problem dims (fixed)
#define Bq 2
#define Vq 8
#define Tq 4
#define Nq 1024
#define Dq 16
#define F_INq 64
#define F_OUTq 64
#define Rq 16
#define RVq 4
#define BV (Bq*Vq)                 // 16
#define ROWS_PER_BV (Tq*Nq*Dq)     // 65536
#define RPB 128                    // rows per block
#define TPB 128                    // threads per block
#define XSTR 65                    // x smem row stride (floats), odd -> conflict-free scalar
#define YSTR 17                    // y smem row stride (floats)

// Precomputed: per-(b,v) H = (sum_A fv[A]*core[A]) @ fac_out  -> (16 x 64),
// and fac_in^T laid out [a][r] (64 x 16)
__device__ float g_H[BV * Rq * F_OUTq];     // 16*16*64
__device__ float g_finT[F_INq * Rq];        // 64*16

// ---- packed f32x2 helpers -------------------------------------------------
__device__ __forceinline__ unsigned long long ffma2(unsigned long long a,
                                                    unsigned long long b,
                                                    unsigned long long c) {
    unsigned long long d;
    asm("fma.rn.f32x2 %0, %1, %2, %3;" : "=l"(d) : "l"(a), "l"(b), "l"(c));
    return d;
}
__device__ __forceinline__ unsigned long long pack2(float lo, float hi) {
    unsigned long long d;
    asm("mov.b64 %0, {%1, %2};" : "=l"(d) : "f"(lo), "f"(hi));
    return d;
}
__device__ __forceinline__ void unpack2(unsigned long long v, float& lo, float& hi) {
    asm("mov.b64 {%0, %1}, %2;" : "=f"(lo), "=f"(hi) : "l"(v));
}

// ---- tiny precompute: Ceff and H per (b,v), plus fac_in^T -----------------
__global__ void precompute_kernel(const int* __restrict__ var_idx,
                                  const float* __restrict__ core,        // (RV, R, R)
                                  const float* __restrict__ factor_vars, // (NVAR, RV)
                                  const float* __restrict__ fac_in,      // (R, F_IN)
                                  const float* __restrict__ fac_out) {   // (R, F_OUT)
    int bv = blockIdx.x;       // 0..15
    int e  = threadIdx.x;      // 0..63
    __shared__ float fvs[RVq];
    __shared__ float ceff[Rq * Rq];

    if (e < RVq) fvs[e] = factor_vars[var_idx[bv] * RVq + e];
    __syncthreads();

    for (int i = e; i < Rq * Rq; i += 64) {
        float s = 0.f;
        #pragma unroll
        for (int A = 0; A < RVq; ++A) s += fvs[A] * core[A * Rq * Rq + i];
        ceff[i] = s;
    }
    __syncthreads();

    #pragma unroll
    for (int r = 0; r < Rq; ++r) {
        float s = 0.f;
        #pragma unroll
        for (int c = 0; c < Rq; ++c) s += ceff[r * Rq + c] * fac_out[c * F_OUTq + e];
        g_H[bv * Rq * F_OUTq + r * F_OUTq + e] = s;
    }
    if (bv == 0) {
        #pragma unroll
        for (int r = 0; r < Rq; ++r) g_finT[e * Rq + r] = fac_in[r * F_INq + e];
    }
}

// ---- main fused kernel -----------------------------------------------------
// out[row, e] = sum_r ( sum_a x[row, a] * finT[a][r] ) * H[bv][r][e]
__global__ void __launch_bounds__(TPB, 4)
tucker_main_kernel(const float* __restrict__ x, float* __restrict__ out) {
    __shared__ float xs[RPB * XSTR];       // 33280 B
    __shared__ float sy[RPB * YSTR];       // 8704 B
    __shared__ float sfw[Rq * F_OUTq];     // 4096 B: finT in phase 1, H in phase 2

    const int bv = blockIdx.y;
    const int t  = threadIdx.x;
    const size_t base = ((size_t)bv * ROWS_PER_BV + (size_t)blockIdx.x * RPB) * (size_t)F_INq;

    // load finT [a][r] (1024 floats)
    #pragma unroll
    for (int i = 0; i < 8; ++i) sfw[i * TPB + t] = g_finT[i * TPB + t];

    // stage x tile (32 KB) via LDG.128 -> scalar STS into stride-65 rows
    const float4* gx = (const float4*)(x + base);
    #pragma unroll
    for (int it = 0; it < 16; ++it) {
        int i = it * TPB + t;
        float4 v = gx[i];
        float* p = &xs[(i >> 4) * XSTR + (i & 15) * 4];
        p[0] = v.x; p[1] = v.y; p[2] = v.z; p[3] = v.w;
    }
    __syncthreads();

    // ---- phase 1: y[row][r] = sum_a x[row][a] * finT[a][r]
    // thread tile: 4 rows (rg) x 4 r-values (jg, 2 f32x2 pairs)
    {
        const int rg = t >> 2, jg = t & 3;
        unsigned long long ya[4][2];
        #pragma unroll
        for (int i = 0; i < 4; ++i) { ya[i][0] = 0ull; ya[i][1] = 0ull; }

        #pragma unroll 4
        for (int a = 0; a < F_INq; ++a) {
            ulonglong2 f = *(const ulonglong2*)&sfw[a * Rq + jg * 4];  // 4 r-values
            #pragma unroll
            for (int i = 0; i < 4; ++i) {
                float xa = xs[(4 * rg + i) * XSTR + a];
                unsigned long long xa2 = pack2(xa, xa);
                ya[i][0] = ffma2(xa2, f.x, ya[i][0]);
                ya[i][1] = ffma2(xa2, f.y, ya[i][1]);
            }
        }
        #pragma unroll
        for (int i = 0; i < 4; ++i) {
            float l0, h0, l1, h1;
            unpack2(ya[i][0], l0, h0);
            unpack2(ya[i][1], l1, h1);
            float* yp = &sy[(4 * rg + i) * YSTR + 4 * jg];
            yp[0] = l0; yp[1] = h0; yp[2] = l1; yp[3] = h1;
        }
    }
    __syncthreads();

    // swap weight buffer: load H[bv] (1024 floats) into sfw
    #pragma unroll
    for (int i = 0; i < 8; ++i) sfw[i * TPB + t] = g_H[bv * Rq * F_OUTq + i * TPB + t];
    __syncthreads();

    // ---- phase 2: out[row][e] = sum_r y[row][r] * H[r][e]
    // thread tile: 8 rows (rg) x 8 e-values (eg, 4 f32x2 pairs)
    {
        const int rg = t >> 3, eg = t & 7;
        unsigned long long o2[8][4];
        #pragma unroll
        for (int i = 0; i < 8; ++i)
            #pragma unroll
            for (int j = 0; j < 4; ++j) o2[i][j] = 0ull;

        #pragma unroll
        for (int r = 0; r < Rq; ++r) {
            const ulonglong2* hp = (const ulonglong2*)&sfw[r * F_OUTq + eg * 8];
            ulonglong2 h0 = hp[0];
            ulonglong2 h1 = hp[1];
            #pragma unroll
            for (int i = 0; i < 8; ++i) {
                float yv = sy[(8 * rg + i) * YSTR + r];
                unsigned long long y2 = pack2(yv, yv);
                o2[i][0] = ffma2(y2, h0.x, o2[i][0]);
                o2[i][1] = ffma2(y2, h0.y, o2[i][1]);
                o2[i][2] = ffma2(y2, h1.x, o2[i][2]);
                o2[i][3] = ffma2(y2, h1.y, o2[i][3]);
            }
        }

        // direct global store: 8 rows x 8 e per thread, 2 x STG.128 per row
        float* ob = out + base;
        #pragma unroll
        for (int i = 0; i < 8; ++i) {
            float* p = ob + (size_t)(8 * rg + i) * F_OUTq + eg * 8;
            *(ulonglong2*)(p)     = make_ulonglong2(o2[i][0], o2[i][1]);
            *(ulonglong2*)(p + 4) = make_ulonglong2(o2[i][2], o2[i][3]);
        }
    }
}

extern "C" void kernel_launch(void* const* d_in, const int* in_sizes, int n_in,
                              void* d_out, int out_size) {
    const float* x           = (const float*)d_in[0];
    const int*   var_idx     = (const int*)d_in[1];
    const float* core        = (const float*)d_in[2];
    const float* factor_vars = (const float*)d_in[3];
    const float* fac_in      = (const float*)d_in[4];
    const float* fac_out     = (const float*)d_in[5];
    float* out = (float*)d_out;

    precompute_kernel<<<BV, 64>>>(var_idx, core, factor_vars, fac_in, fac_out);

    dim3 grid(ROWS_PER_BV / RPB, BV);   // (512, 16)
    tucker_main_kernel<<<grid, TPB>>>(x, out);
}